// round 1
// baseline (speedup 1.0000x reference)
#include <cuda_runtime.h>
#include <math.h>

#define D_  1024
#define S_  1024
#define B_  2
#define H_  16
#define DH_ 64
#define FF_ 4096
#define V_  32000
#define L_  12
#define ROWS_ (B_*S_)   // 2048

// ---------------- scratch (static device globals; no allocation allowed) ----
__device__ float g_h  [ROWS_*D_];        // residual stream
__device__ float g_q  [ROWS_*D_];
__device__ float g_k  [ROWS_*D_];
__device__ float g_v  [ROWS_*D_];
__device__ float g_ctx[ROWS_*D_];        // attention ctx / ff2 output
__device__ float g_ff [ROWS_*FF_];       // ff intermediate
__device__ float g_sc [(size_t)B_*H_*S_*S_];  // attention scores/probs (128 MB)

// ---------------- generic 128x128x8 SGEMM body (A,B row-major, C=A@B+bias) --
template<int ACT>  // 0 = none, 1 = exact GELU
__device__ __forceinline__ void gemm_body(const float* __restrict__ A,
                                          const float* __restrict__ Bm,
                                          const float* __restrict__ bias,
                                          float* __restrict__ C,
                                          int N, int K, int brow, int bcol)
{
    __shared__ float As[8][128];
    __shared__ float Bs[8][128];
    const int tid  = threadIdx.x;
    const int aRow = tid >> 1;
    const int aCol = (tid & 1) << 2;
    const int bRow = tid >> 5;
    const int bCol = (tid & 31) << 2;
    const int tx   = tid & 15;
    const int ty   = tid >> 4;

    const float* Ab = A  + (size_t)brow * 128 * K;
    const float* Bb = Bm + (size_t)bcol * 128;

    float acc[8][8];
#pragma unroll
    for (int i = 0; i < 8; i++)
#pragma unroll
        for (int j = 0; j < 8; j++) acc[i][j] = 0.f;

    for (int k0 = 0; k0 < K; k0 += 8) {
        float4 av = *(const float4*)(Ab + (size_t)aRow * K + k0 + aCol);
        As[aCol+0][aRow] = av.x;
        As[aCol+1][aRow] = av.y;
        As[aCol+2][aRow] = av.z;
        As[aCol+3][aRow] = av.w;
        float4 bv = *(const float4*)(Bb + (size_t)(k0 + bRow) * N + bCol);
        *(float4*)&Bs[bRow][bCol] = bv;
        __syncthreads();
#pragma unroll
        for (int kk = 0; kk < 8; kk++) {
            float4 a0 = *(const float4*)&As[kk][ty*4];
            float4 a1 = *(const float4*)&As[kk][ty*4 + 64];
            float4 b0 = *(const float4*)&Bs[kk][tx*4];
            float4 b1 = *(const float4*)&Bs[kk][tx*4 + 64];
            float ar[8] = {a0.x,a0.y,a0.z,a0.w,a1.x,a1.y,a1.z,a1.w};
            float br[8] = {b0.x,b0.y,b0.z,b0.w,b1.x,b1.y,b1.z,b1.w};
#pragma unroll
            for (int i = 0; i < 8; i++)
#pragma unroll
                for (int j = 0; j < 8; j++)
                    acc[i][j] = fmaf(ar[i], br[j], acc[i][j]);
        }
        __syncthreads();
    }

    float bvals[8];
    if (bias) {
        const float* bp = bias + (size_t)bcol * 128;
#pragma unroll
        for (int j = 0; j < 4; j++) {
            bvals[j]   = bp[tx*4 + j];
            bvals[4+j] = bp[tx*4 + 64 + j];
        }
    } else {
#pragma unroll
        for (int j = 0; j < 8; j++) bvals[j] = 0.f;
    }
#pragma unroll
    for (int i = 0; i < 8; i++) {
        int r = brow*128 + ((i < 4) ? (ty*4 + i) : (ty*4 + 64 + i - 4));
        float out[8];
#pragma unroll
        for (int j = 0; j < 8; j++) {
            float vx = acc[i][j] + bvals[j];
            if (ACT == 1)
                vx = vx * 0.5f * (1.0f + erff(vx * 0.70710678118654752f));
            out[j] = vx;
        }
        float* Cp = C + (size_t)r * N + (size_t)bcol * 128;
        *(float4*)(Cp + tx*4)      = make_float4(out[0], out[1], out[2], out[3]);
        *(float4*)(Cp + tx*4 + 64) = make_float4(out[4], out[5], out[6], out[7]);
    }
}

template<int ACT>
__global__ __launch_bounds__(256) void gemm_kernel(const float* __restrict__ A,
                                                   const float* __restrict__ Bm,
                                                   const float* __restrict__ bias,
                                                   float* __restrict__ C,
                                                   int N, int K)
{
    gemm_body<ACT>(A, Bm, bias, C, N, K, blockIdx.y, blockIdx.x);
}

// z-batched QKV projection (3 GEMMs in one launch)
__global__ __launch_bounds__(256) void qkv_kernel(const float* __restrict__ A,
                                                  const float* __restrict__ Wq,
                                                  const float* __restrict__ Wk,
                                                  const float* __restrict__ Wv,
                                                  const float* __restrict__ bq,
                                                  const float* __restrict__ bk,
                                                  const float* __restrict__ bv)
{
    const float* W; const float* bb; float* C;
    if (blockIdx.z == 0)      { W = Wq; bb = bq; C = g_q; }
    else if (blockIdx.z == 1) { W = Wk; bb = bk; C = g_k; }
    else                      { W = Wv; bb = bv; C = g_v; }
    gemm_body<0>(A, W, bb, C, D_, D_, blockIdx.y, blockIdx.x);
}

// ---------------- scores = scale * Q @ K^T + mask_bias  (NT GEMM, K=64) -----
__global__ __launch_bounds__(256) void score_gemm_kernel(const float* __restrict__ mask)
{
    const int z  = blockIdx.z;          // b*H + h
    const int b  = z >> 4;
    const int hh = z & 15;
    const float* A  = g_q + (size_t)b * S_ * D_ + hh * DH_;   // [1024,64], lda=D
    const float* Bp = g_k + (size_t)b * S_ * D_ + hh * DH_;   // [1024,64], ldb=D
    float* C = g_sc + (size_t)z * S_ * S_;                    // [1024,1024]

    const int brow = blockIdx.y, bcol = blockIdx.x;
    __shared__ float As[8][128];
    __shared__ float Bs[8][128];
    const int tid  = threadIdx.x;
    const int lRow = tid >> 1;
    const int lCol = (tid & 1) << 2;
    const int tx   = tid & 15;
    const int ty   = tid >> 4;

    const float* Ab = A  + (size_t)(brow * 128) * D_;
    const float* Bb = Bp + (size_t)(bcol * 128) * D_;

    float acc[8][8];
#pragma unroll
    for (int i = 0; i < 8; i++)
#pragma unroll
        for (int j = 0; j < 8; j++) acc[i][j] = 0.f;

    for (int k0 = 0; k0 < DH_; k0 += 8) {
        float4 av = *(const float4*)(Ab + (size_t)lRow * D_ + k0 + lCol);
        As[lCol+0][lRow] = av.x; As[lCol+1][lRow] = av.y;
        As[lCol+2][lRow] = av.z; As[lCol+3][lRow] = av.w;
        float4 bv = *(const float4*)(Bb + (size_t)lRow * D_ + k0 + lCol);
        Bs[lCol+0][lRow] = bv.x; Bs[lCol+1][lRow] = bv.y;
        Bs[lCol+2][lRow] = bv.z; Bs[lCol+3][lRow] = bv.w;
        __syncthreads();
#pragma unroll
        for (int kk = 0; kk < 8; kk++) {
            float4 a0 = *(const float4*)&As[kk][ty*4];
            float4 a1 = *(const float4*)&As[kk][ty*4 + 64];
            float4 b0 = *(const float4*)&Bs[kk][tx*4];
            float4 b1 = *(const float4*)&Bs[kk][tx*4 + 64];
            float ar[8] = {a0.x,a0.y,a0.z,a0.w,a1.x,a1.y,a1.z,a1.w};
            float br[8] = {b0.x,b0.y,b0.z,b0.w,b1.x,b1.y,b1.z,b1.w};
#pragma unroll
            for (int i = 0; i < 8; i++)
#pragma unroll
                for (int j = 0; j < 8; j++)
                    acc[i][j] = fmaf(ar[i], br[j], acc[i][j]);
        }
        __syncthreads();
    }

    float biasv[8];
#pragma unroll
    for (int j = 0; j < 4; j++) {
        int n0 = bcol*128 + tx*4 + j;
        biasv[j]   = (1.0f - mask[b*S_ + n0])      * -10000.0f;
        biasv[4+j] = (1.0f - mask[b*S_ + n0 + 64]) * -10000.0f;
    }
#pragma unroll
    for (int i = 0; i < 8; i++) {
        int r = brow*128 + ((i < 4) ? (ty*4 + i) : (ty*4 + 64 + i - 4));
        float out[8];
#pragma unroll
        for (int j = 0; j < 8; j++) out[j] = acc[i][j] * 0.125f + biasv[j];
        float* Cp = C + (size_t)r * S_ + bcol * 128;
        *(float4*)(Cp + tx*4)      = make_float4(out[0], out[1], out[2], out[3]);
        *(float4*)(Cp + tx*4 + 64) = make_float4(out[4], out[5], out[6], out[7]);
    }
}

// ---------------- row softmax over g_sc (in place) --------------------------
__global__ __launch_bounds__(256) void softmax_kernel()
{
    const size_t base = (size_t)blockIdx.x * S_;
    const int tid = threadIdx.x;
    float x[4];
    float mx = -1e30f;
#pragma unroll
    for (int i = 0; i < 4; i++) {
        x[i] = g_sc[base + tid + i*256];
        mx = fmaxf(mx, x[i]);
    }
#pragma unroll
    for (int off = 16; off; off >>= 1)
        mx = fmaxf(mx, __shfl_xor_sync(0xffffffffu, mx, off));
    __shared__ float red[8];
    if ((tid & 31) == 0) red[tid >> 5] = mx;
    __syncthreads();
    if (tid == 0) {
        float v = red[0];
#pragma unroll
        for (int i = 1; i < 8; i++) v = fmaxf(v, red[i]);
        red[0] = v;
    }
    __syncthreads();
    mx = red[0];
    __syncthreads();

    float sum = 0.f;
#pragma unroll
    for (int i = 0; i < 4; i++) { x[i] = expf(x[i] - mx); sum += x[i]; }
#pragma unroll
    for (int off = 16; off; off >>= 1)
        sum += __shfl_xor_sync(0xffffffffu, sum, off);
    if ((tid & 31) == 0) red[tid >> 5] = sum;
    __syncthreads();
    if (tid == 0) {
        float v = 0.f;
#pragma unroll
        for (int i = 0; i < 8; i++) v += red[i];
        red[0] = 1.0f / v;
    }
    __syncthreads();
    const float inv = red[0];
#pragma unroll
    for (int i = 0; i < 4; i++) g_sc[base + tid + i*256] = x[i] * inv;
}

// ---------------- ctx = P @ V  (M=1024,N=64,K=1024; BM=128,BN=64,BK=16) -----
__global__ __launch_bounds__(256) void ctx_gemm_kernel()
{
    const int z  = blockIdx.z;
    const int b  = z >> 4;
    const int hh = z & 15;
    const float* A  = g_sc  + (size_t)z * S_ * S_;             // lda = S_
    const float* Bp = g_v   + (size_t)b * S_ * D_ + hh * DH_;  // ldb = D_
    float*       C  = g_ctx + (size_t)b * S_ * D_ + hh * DH_;  // ldc = D_
    const int brow = blockIdx.y;

    __shared__ float As[16][128];
    __shared__ float Bs[16][64];
    const int tid = threadIdx.x;
    const int tx  = tid & 15;
    const int ty  = tid >> 4;

    float acc[8][4];
#pragma unroll
    for (int i = 0; i < 8; i++)
#pragma unroll
        for (int j = 0; j < 4; j++) acc[i][j] = 0.f;

    for (int k0 = 0; k0 < S_; k0 += 16) {
#pragma unroll
        for (int t = 0; t < 2; t++) {
            int idx = tid + t*256;             // 0..511 float4s of A tile
            int r   = idx >> 2;
            int c4  = (idx & 3) << 2;
            float4 av = *(const float4*)(A + (size_t)(brow*128 + r) * S_ + k0 + c4);
            As[c4+0][r] = av.x; As[c4+1][r] = av.y;
            As[c4+2][r] = av.z; As[c4+3][r] = av.w;
        }
        {
            int r  = tid >> 4;
            int c4 = (tid & 15) << 2;
            float4 bv = *(const float4*)(Bp + (size_t)(k0 + r) * D_ + c4);
            *(float4*)&Bs[r][c4] = bv;
        }
        __syncthreads();
#pragma unroll
        for (int kk = 0; kk < 16; kk++) {
            float4 a0 = *(const float4*)&As[kk][ty*4];
            float4 a1 = *(const float4*)&As[kk][ty*4 + 64];
            float4 b0 = *(const float4*)&Bs[kk][tx*4];
            float ar[8] = {a0.x,a0.y,a0.z,a0.w,a1.x,a1.y,a1.z,a1.w};
            float br[4] = {b0.x,b0.y,b0.z,b0.w};
#pragma unroll
            for (int i = 0; i < 8; i++)
#pragma unroll
                for (int j = 0; j < 4; j++)
                    acc[i][j] = fmaf(ar[i], br[j], acc[i][j]);
        }
        __syncthreads();
    }
#pragma unroll
    for (int i = 0; i < 8; i++) {
        int r = brow*128 + ((i < 4) ? (ty*4 + i) : (ty*4 + 64 + i - 4));
        *(float4*)(C + (size_t)r * D_ + tx*4) =
            make_float4(acc[i][0], acc[i][1], acc[i][2], acc[i][3]);
    }
}

// ---------------- LayerNorm helpers -----------------------------------------
__device__ __forceinline__ void ln_stats(float s, float ss, float& mean, float& rstd)
{
#pragma unroll
    for (int off = 16; off; off >>= 1) {
        s  += __shfl_xor_sync(0xffffffffu, s,  off);
        ss += __shfl_xor_sync(0xffffffffu, ss, off);
    }
    __shared__ float rs[8], rss[8];
    const int w = threadIdx.x >> 5;
    if ((threadIdx.x & 31) == 0) { rs[w] = s; rss[w] = ss; }
    __syncthreads();
    if (threadIdx.x == 0) {
        float a = 0.f, bb = 0.f;
#pragma unroll
        for (int i = 0; i < 8; i++) { a += rs[i]; bb += rss[i]; }
        float mu  = a * (1.0f / 1024.0f);
        float var = bb * (1.0f / 1024.0f) - mu * mu;
        rs[0]  = mu;
        rss[0] = rsqrtf(var + 1e-5f);
    }
    __syncthreads();
    mean = rs[0];
    rstd = rss[0];
}

__global__ __launch_bounds__(256) void embed_ln_kernel(const int* __restrict__ ids,
                                                       const float* __restrict__ tok,
                                                       const float* __restrict__ pos,
                                                       const float* __restrict__ g,
                                                       const float* __restrict__ be)
{
    const int row  = blockIdx.x;
    const int spos = row & (S_ - 1);
    const size_t tbase = (size_t)ids[row] * D_;
    const size_t pbase = (size_t)spos * D_;
    float x[4]; float s = 0.f, ss = 0.f;
#pragma unroll
    for (int i = 0; i < 4; i++) {
        int idx = threadIdx.x + i*256;
        x[i] = tok[tbase + idx] + pos[pbase + idx];
        s += x[i]; ss += x[i]*x[i];
    }
    float mean, rstd;
    ln_stats(s, ss, mean, rstd);
    const size_t base = (size_t)row * D_;
#pragma unroll
    for (int i = 0; i < 4; i++) {
        int idx = threadIdx.x + i*256;
        g_h[base + idx] = (x[i] - mean) * rstd * g[idx] + be[idx];
    }
}

__global__ __launch_bounds__(256) void add_ln_kernel(float* __restrict__ h,
                                                     const float* __restrict__ add,
                                                     const float* __restrict__ g,
                                                     const float* __restrict__ be)
{
    const size_t base = (size_t)blockIdx.x * D_;
    float x[4]; float s = 0.f, ss = 0.f;
#pragma unroll
    for (int i = 0; i < 4; i++) {
        int idx = threadIdx.x + i*256;
        x[i] = h[base + idx] + add[base + idx];
        s += x[i]; ss += x[i]*x[i];
    }
    float mean, rstd;
    ln_stats(s, ss, mean, rstd);
#pragma unroll
    for (int i = 0; i < 4; i++) {
        int idx = threadIdx.x + i*256;
        h[base + idx] = (x[i] - mean) * rstd * g[idx] + be[idx];
    }
}

// ---------------- driver ----------------------------------------------------
extern "C" void kernel_launch(void* const* d_in, const int* in_sizes, int n_in,
                              void* d_out, int out_size)
{
    (void)in_sizes; (void)n_in; (void)out_size;
    const int*   ids  = (const int*)  d_in[0];
    const float* mask = (const float*)d_in[1];
    const float* tok  = (const float*)d_in[2];
    const float* pos  = (const float*)d_in[3];
    const float* ln0g = (const float*)d_in[4];
    const float* ln0b = (const float*)d_in[5];
    const float* Wq   = (const float*)d_in[6];
    const float* bq   = (const float*)d_in[7];
    const float* Wk   = (const float*)d_in[8];
    const float* bk   = (const float*)d_in[9];
    const float* Wv   = (const float*)d_in[10];
    const float* bv   = (const float*)d_in[11];
    const float* ln1g = (const float*)d_in[12];
    const float* ln1b = (const float*)d_in[13];
    const float* W1   = (const float*)d_in[14];
    const float* b1   = (const float*)d_in[15];
    const float* W2   = (const float*)d_in[16];
    const float* b2   = (const float*)d_in[17];
    const float* ln2g = (const float*)d_in[18];
    const float* ln2b = (const float*)d_in[19];
    const float* Wlm  = (const float*)d_in[20];

    float *h, *ctx, *ff;
    cudaGetSymbolAddress((void**)&h,   g_h);
    cudaGetSymbolAddress((void**)&ctx, g_ctx);
    cudaGetSymbolAddress((void**)&ff,  g_ff);

    embed_ln_kernel<<<ROWS_, 256>>>(ids, tok, pos, ln0g, ln0b);

    for (int l = 0; l < L_; l++) {
        qkv_kernel<<<dim3(D_/128, ROWS_/128, 3), 256>>>(
            h,
            Wq + (size_t)l * D_ * D_, Wk + (size_t)l * D_ * D_, Wv + (size_t)l * D_ * D_,
            bq + (size_t)l * D_,      bk + (size_t)l * D_,      bv + (size_t)l * D_);

        score_gemm_kernel<<<dim3(S_/128, S_/128, B_*H_), 256>>>(mask);
        softmax_kernel<<<B_*H_*S_, 256>>>();
        ctx_gemm_kernel<<<dim3(1, S_/128, B_*H_), 256>>>();

        add_ln_kernel<<<ROWS_, 256>>>(h, ctx, ln1g + (size_t)l * D_, ln1b + (size_t)l * D_);

        gemm_kernel<1><<<dim3(FF_/128, ROWS_/128), 256>>>(
            h, W1 + (size_t)l * D_ * FF_, b1 + (size_t)l * FF_, ff, FF_, D_);
        gemm_kernel<0><<<dim3(D_/128, ROWS_/128), 256>>>(
            ff, W2 + (size_t)l * FF_ * D_, b2 + (size_t)l * D_, ctx, D_, FF_);

        add_ln_kernel<<<ROWS_, 256>>>(h, ctx, ln2g + (size_t)l * D_, ln2b + (size_t)l * D_);
    }

    gemm_kernel<0><<<dim3(V_/128, ROWS_/128), 256>>>(
        h, Wlm, (const float*)nullptr, (float*)d_out, V_, D_);
}

// round 7
// speedup vs baseline: 1.6207x; 1.6207x over previous
#include <cuda_runtime.h>
#include <cuda_bf16.h>
#include <math.h>
#include <stdint.h>

typedef __nv_bfloat16 bf16;

#define D_  1024
#define S_  1024
#define B_  2
#define H_  16
#define DH_ 64
#define FF_ 4096
#define V_  32000
#define L_  12
#define ROWS_ (B_*S_)   // 2048
#define KA_D  3072      // 3*D
#define KA_FF 12288     // 3*FF
#define KA_DH 192       // 3*DH

// ======================= scratch (device globals) ===========================
__device__ __align__(256) float g_h  [ROWS_*D_];
__device__ __align__(256) float g_v  [ROWS_*D_];
__device__ __align__(256) float g_ctx[ROWS_*D_];
__device__ __align__(256) float g_sc [(size_t)B_*H_*S_*S_];

__device__ __align__(256) bf16 g_aa [(size_t)ROWS_*KA_D];            // A-layout acts
__device__ __align__(256) bf16 g_qa [(size_t)B_*H_*S_*KA_DH];        // Q aug per head
__device__ __align__(256) bf16 g_ka [(size_t)B_*H_*S_*KA_DH];        // K aug per head
__device__ __align__(256) bf16 g_va [(size_t)B_*H_*DH_*KA_D];        // V^T aug
__device__ __align__(256) bf16 g_ffa[(size_t)ROWS_*KA_FF];           // gelu out aug
__device__ __align__(256) bf16 g_pa [(size_t)B_*H_*S_*KA_D];         // probs aug

__device__ __align__(256) bf16 g_wq [(size_t)L_*D_*KA_D];
__device__ __align__(256) bf16 g_wk [(size_t)L_*D_*KA_D];
__device__ __align__(256) bf16 g_wv [(size_t)L_*D_*KA_D];
__device__ __align__(256) bf16 g_w1 [(size_t)L_*FF_*KA_D];
__device__ __align__(256) bf16 g_w2 [(size_t)L_*D_*KA_FF];
__device__ __align__(256) bf16 g_wlm[(size_t)V_*KA_D];

// ======================= helpers ============================================
__device__ __forceinline__ uint32_t smem_to_u32(const void* p) {
    uint32_t a;
    asm("{ .reg .u64 t; cvta.to.shared.u64 t, %1; cvt.u32.u64 %0, t; }"
        : "=r"(a) : "l"(p));
    return a;
}
__device__ __forceinline__ void cp16(bf16* s, const bf16* g) {
    uint32_t sa = smem_to_u32(s);
    asm volatile("cp.async.cg.shared.global [%0], [%1], 16;" :: "r"(sa), "l"(g));
}
#define CP_COMMIT() asm volatile("cp.async.commit_group;" ::: "memory")

#define LDSM4(R0,R1,R2,R3,ADDR) \
    asm volatile("ldmatrix.sync.aligned.m8n8.x4.shared.b16 {%0,%1,%2,%3}, [%4];" \
        : "=r"(R0), "=r"(R1), "=r"(R2), "=r"(R3) : "r"(ADDR))

#define MMA16816(C0,C1,C2,C3,A0,A1,A2,A3,B0,B1) \
    asm volatile("mma.sync.aligned.m16n8k16.row.col.f32.bf16.bf16.f32 " \
        "{%0,%1,%2,%3}, {%4,%5,%6,%7}, {%8,%9}, {%0,%1,%2,%3};" \
        : "+f"(C0), "+f"(C1), "+f"(C2), "+f"(C3) \
        : "r"(A0), "r"(A1), "r"(A2), "r"(A3), "r"(B0), "r"(B1))

__device__ __forceinline__ void split2(float v, bf16& h, bf16& l) {
    h = __float2bfloat16(v);
    l = __float2bfloat16(v - __bfloat162float(h));
}

// ======================= epilogue functors ==================================
struct EpiF32 {      // fp32 out (+opt bias)
    float* C; const float* bias; int ldc;
    __device__ void operator()(int z, int r, int c, float v) const {
        if (bias) v += bias[c];
        C[(size_t)r*ldc + c] = v;
    }
};
struct EpiQs {       // Q: bias + split -> g_qa per-head (h,l,h)
    const float* bias;
    __device__ void operator()(int z, int r, int c, float v) const {
        v += bias[c];
        int hh = c >> 6, d = c & 63;
        int b = r >> 10, s = r & 1023;
        size_t base = ((size_t)((b << 4) + hh) * S_ + s) * KA_DH + d;
        bf16 h, l; split2(v, h, l);
        g_qa[base] = h; g_qa[base + 64] = l; g_qa[base + 128] = h;
    }
};
struct EpiKs {       // K: bias + split -> g_ka per-head (h,h,l)
    const float* bias;
    __device__ void operator()(int z, int r, int c, float v) const {
        v += bias[c];
        int hh = c >> 6, d = c & 63;
        int b = r >> 10, s = r & 1023;
        size_t base = ((size_t)((b << 4) + hh) * S_ + s) * KA_DH + d;
        bf16 h, l; split2(v, h, l);
        g_ka[base] = h; g_ka[base + 64] = h; g_ka[base + 128] = l;
    }
};
struct EpiGelu {     // FF1: bias + gelu + split -> g_ffa (h,l,h)
    const float* bias;
    __device__ void operator()(int z, int r, int c, float v) const {
        v += bias[c];
        v = v * 0.5f * (1.0f + erff(v * 0.70710678118654752f));
        bf16 h, l; split2(v, h, l);
        size_t base = (size_t)r * KA_FF + c;
        g_ffa[base] = h; g_ffa[base + FF_] = l; g_ffa[base + 2*FF_] = h;
    }
};
struct EpiScore {    // scores: scale + mask bias -> g_sc fp32
    const float* mask;
    __device__ void operator()(int z, int r, int c, float v) const {
        int b = z >> 4;
        g_sc[(size_t)z*S_*S_ + (size_t)r*S_ + c] =
            v * 0.125f + (1.0f - mask[b*S_ + c]) * -10000.0f;
    }
};
struct EpiCtx {      // ctx: fp32 -> g_ctx at head cols
    __device__ void operator()(int z, int r, int c, float v) const {
        int b = z >> 4, hh = z & 15;
        g_ctx[((size_t)(b * S_) + r) * D_ + hh*64 + c] = v;
    }
};

// ======================= pipelined mma.sync GEMM ============================
// C[128 x BN] = A[128,K] @ B[BN,K]^T   (A,B row-major K-major, bf16, fp32 acc)
template<int BN>
__device__ __forceinline__ void load_stage(const bf16* Ap, const bf16* Bp,
                                           bf16* As, bf16* Bs,
                                           int st, int k0, int K, int tid)
{
    constexpr int LDS = 40, ASZ = 128*LDS, BSZ = BN*LDS;
    {
        int row = tid >> 1, cb = (tid & 1) << 1;
#pragma unroll
        for (int i = 0; i < 2; i++) {
            int cc = cb + i;
            cp16(As + st*ASZ + row*LDS + cc*8, Ap + (size_t)row*K + k0 + cc*8);
        }
    }
    if (BN == 128) {
        int row = tid >> 1, cb = (tid & 1) << 1;
#pragma unroll
        for (int i = 0; i < 2; i++) {
            int cc = cb + i;
            cp16(Bs + st*BSZ + row*LDS + cc*8, Bp + (size_t)row*K + k0 + cc*8);
        }
    } else {  // BN == 64
        int row = tid >> 2, cc = tid & 3;
        cp16(Bs + st*BSZ + row*LDS + cc*8, Bp + (size_t)row*K + k0 + cc*8);
    }
    CP_COMMIT();
}

template<int BN, class Epi>
__global__ __launch_bounds__(256, 2)
void gemm_k(const bf16* __restrict__ A, const bf16* __restrict__ B, int K,
            size_t sA, size_t sB, Epi epi)
{
    constexpr int NT  = BN / 32;       // n-tiles (of 8) per warp
    constexpr int LDS = 40;
    constexpr int ASZ = 128*LDS, BSZ = BN*LDS;
    extern __shared__ bf16 sm[];
    bf16* As = sm;
    bf16* Bs = sm + 3*ASZ;

    const int z = blockIdx.z;
    const bf16* Ap = A + (size_t)z*sA + (size_t)blockIdx.y * 128 * K;
    const bf16* Bp = B + (size_t)z*sB + (size_t)blockIdx.x * BN  * K;

    const int tid = threadIdx.x, lane = tid & 31, wid = tid >> 5;
    const int wr = wid >> 2, wc = wid & 3;

    float acc[4][NT][4];
#pragma unroll
    for (int i = 0; i < 4; i++)
#pragma unroll
        for (int j = 0; j < NT; j++)
#pragma unroll
            for (int k = 0; k < 4; k++) acc[i][j][k] = 0.f;

    const uint32_t smBase = smem_to_u32(sm);
    const uint32_t aOff = (((lane & 15)*LDS) + ((lane >> 4) & 1)*8) * 2;
    const uint32_t bOff = ((((lane & 7) + ((lane >> 4) << 3))*LDS) + ((lane >> 3) & 1)*8) * 2;

    const int NK = K >> 5;
    load_stage<BN>(Ap, Bp, As, Bs, 0, 0,  K, tid);
    load_stage<BN>(Ap, Bp, As, Bs, 1, 32, K, tid);

    for (int it = 0; it < NK; it++) {
        if (it + 1 == NK) asm volatile("cp.async.wait_group 0;" ::: "memory");
        else              asm volatile("cp.async.wait_group 1;" ::: "memory");
        __syncthreads();
        const int nx = it + 2;
        if (nx < NK) load_stage<BN>(Ap, Bp, As, Bs, nx % 3, nx << 5, K, tid);

        const int st = it % 3;
        const uint32_t aS = smBase + (uint32_t)(st*ASZ + wr*64*LDS)*2 + aOff;
        const uint32_t bS = smBase + (uint32_t)(3*ASZ + st*BSZ + wc*(BN/4)*LDS)*2 + bOff;
#pragma unroll
        for (int kk = 0; kk < 2; kk++) {
            uint32_t af[4][4];
#pragma unroll
            for (int mt = 0; mt < 4; mt++)
                LDSM4(af[mt][0], af[mt][1], af[mt][2], af[mt][3],
                      aS + (uint32_t)(mt*16*LDS + kk*16)*2);
            uint32_t bfr[NT][2];
#pragma unroll
            for (int np = 0; np < NT/2; np++) {
                uint32_t r0, r1, r2, r3;
                LDSM4(r0, r1, r2, r3, bS + (uint32_t)(np*16*LDS + kk*16)*2);
                bfr[2*np][0] = r0; bfr[2*np][1] = r1;
                bfr[2*np+1][0] = r2; bfr[2*np+1][1] = r3;
            }
#pragma unroll
            for (int mt = 0; mt < 4; mt++)
#pragma unroll
                for (int nt = 0; nt < NT; nt++)
                    MMA16816(acc[mt][nt][0], acc[mt][nt][1], acc[mt][nt][2], acc[mt][nt][3],
                             af[mt][0], af[mt][1], af[mt][2], af[mt][3],
                             bfr[nt][0], bfr[nt][1]);
        }
    }

    const int lr = lane >> 2, lc = (lane & 3) << 1;
#pragma unroll
    for (int mt = 0; mt < 4; mt++)
#pragma unroll
        for (int nt = 0; nt < NT; nt++) {
            int r0 = blockIdx.y*128 + wr*64 + mt*16 + lr;
            int c0 = blockIdx.x*BN + wc*(BN/4) + nt*8 + lc;
            epi(z, r0,     c0,     acc[mt][nt][0]);
            epi(z, r0,     c0 + 1, acc[mt][nt][1]);
            epi(z, r0 + 8, c0,     acc[mt][nt][2]);
            epi(z, r0 + 8, c0 + 1, acc[mt][nt][3]);
        }
}

// ======================= weight transpose+split (B-layout) ==================
// W[K,N] fp32 -> out[N, 3K] bf16: [Wh | Wh | Wl]
__global__ __launch_bounds__(256) void wsplit_kernel(const float* __restrict__ W,
        bf16* __restrict__ out, int K, int N)
{
    __shared__ float t[32][33];
    const size_t mat  = (size_t)blockIdx.z * K * N;
    const size_t mato = (size_t)blockIdx.z * K * N * 3;
    const int n0 = blockIdx.x*32, k0 = blockIdx.y*32;
    const int tx = threadIdx.x & 31, ty = threadIdx.x >> 5;
#pragma unroll
    for (int i = 0; i < 4; i++) {
        int k = k0 + ty*4 + i;
        t[ty*4+i][tx] = W[mat + (size_t)k*N + n0 + tx];
    }
    __syncthreads();
#pragma unroll
    for (int i = 0; i < 4; i++) {
        int n = n0 + ty*4 + i;
        float v = t[tx][ty*4+i];
        bf16 h, l; split2(v, h, l);
        size_t o = mato + (size_t)n*3*K + k0 + tx;
        out[o] = h; out[o + K] = h; out[o + 2*K] = l;
    }
}

// V [b,s,h*64+d] fp32 -> g_va [z][d][3S]: [Vh | Vh | Vl]
__global__ __launch_bounds__(256) void vtrans_kernel()
{
    __shared__ float t[32][33];
    const int z = blockIdx.z, b = z >> 4, hh = z & 15;
    const int s0 = blockIdx.x*32, d0 = blockIdx.y*32;
    const int tx = threadIdx.x & 31, ty = threadIdx.x >> 5;
#pragma unroll
    for (int i = 0; i < 4; i++) {
        int s = s0 + ty*4 + i;
        t[ty*4+i][tx] = g_v[((size_t)(b*S_) + s)*D_ + hh*64 + d0 + tx];
    }
    __syncthreads();
#pragma unroll
    for (int i = 0; i < 4; i++) {
        int dd = d0 + ty*4 + i;
        float v = t[tx][ty*4+i];
        bf16 h, l; split2(v, h, l);
        size_t o = ((size_t)z*DH_ + dd)*KA_D + s0 + tx;
        g_va[o] = h; g_va[o + S_] = h; g_va[o + 2*S_] = l;
    }
}

// ======================= softmax (fp32 in -> aug bf16 out) ==================
__global__ __launch_bounds__(256) void softmax_split_kernel()
{
    const size_t base = (size_t)blockIdx.x * S_;
    const int tid = threadIdx.x;
    float x[4];
    float mx = -1e30f;
#pragma unroll
    for (int i = 0; i < 4; i++) {
        x[i] = g_sc[base + tid + i*256];
        mx = fmaxf(mx, x[i]);
    }
#pragma unroll
    for (int off = 16; off; off >>= 1)
        mx = fmaxf(mx, __shfl_xor_sync(0xffffffffu, mx, off));
    __shared__ float red[8];
    if ((tid & 31) == 0) red[tid >> 5] = mx;
    __syncthreads();
    if (tid == 0) {
        float v = red[0];
#pragma unroll
        for (int i = 1; i < 8; i++) v = fmaxf(v, red[i]);
        red[0] = v;
    }
    __syncthreads();
    mx = red[0];
    __syncthreads();
    float sum = 0.f;
#pragma unroll
    for (int i = 0; i < 4; i++) { x[i] = expf(x[i] - mx); sum += x[i]; }
#pragma unroll
    for (int off = 16; off; off >>= 1)
        sum += __shfl_xor_sync(0xffffffffu, sum, off);
    if ((tid & 31) == 0) red[tid >> 5] = sum;
    __syncthreads();
    if (tid == 0) {
        float v = 0.f;
#pragma unroll
        for (int i = 0; i < 8; i++) v += red[i];
        red[0] = 1.0f / v;
    }
    __syncthreads();
    const float inv = red[0];
    const size_t ob = (size_t)blockIdx.x * KA_D;
#pragma unroll
    for (int i = 0; i < 4; i++) {
        int idx = tid + i*256;
        float p = x[i] * inv;
        bf16 h, l; split2(p, h, l);
        g_pa[ob + idx] = h; g_pa[ob + S_ + idx] = l; g_pa[ob + 2*S_ + idx] = h;
    }
}

// ======================= LayerNorm (fp32 h + aug split out) =================
__device__ __forceinline__ void ln_stats(float s, float ss, float& mean, float& rstd)
{
#pragma unroll
    for (int off = 16; off; off >>= 1) {
        s  += __shfl_xor_sync(0xffffffffu, s,  off);
        ss += __shfl_xor_sync(0xffffffffu, ss, off);
    }
    __shared__ float rs[8], rss[8];
    const int w = threadIdx.x >> 5;
    if ((threadIdx.x & 31) == 0) { rs[w] = s; rss[w] = ss; }
    __syncthreads();
    if (threadIdx.x == 0) {
        float a = 0.f, bb = 0.f;
#pragma unroll
        for (int i = 0; i < 8; i++) { a += rs[i]; bb += rss[i]; }
        float mu  = a * (1.0f / 1024.0f);
        float var = bb * (1.0f / 1024.0f) - mu * mu;
        rs[0]  = mu;
        rss[0] = rsqrtf(var + 1e-5f);
    }
    __syncthreads();
    mean = rs[0];
    rstd = rss[0];
}

__device__ __forceinline__ void write_act(size_t row, int idx, float y)
{
    g_h[row*D_ + idx] = y;
    bf16 h, l; split2(y, h, l);
    size_t b3 = row*KA_D + idx;
    g_aa[b3] = h; g_aa[b3 + D_] = l; g_aa[b3 + 2*D_] = h;
}

__global__ __launch_bounds__(256) void embed_ln_kernel(const int* __restrict__ ids,
                                                       const float* __restrict__ tok,
                                                       const float* __restrict__ pos,
                                                       const float* __restrict__ g,
                                                       const float* __restrict__ be)
{
    const int row  = blockIdx.x;
    const int spos = row & (S_ - 1);
    const size_t tbase = (size_t)ids[row] * D_;
    const size_t pbase = (size_t)spos * D_;
    float x[4]; float s = 0.f, ss = 0.f;
#pragma unroll
    for (int i = 0; i < 4; i++) {
        int idx = threadIdx.x + i*256;
        x[i] = tok[tbase + idx] + pos[pbase + idx];
        s += x[i]; ss += x[i]*x[i];
    }
    float mean, rstd;
    ln_stats(s, ss, mean, rstd);
#pragma unroll
    for (int i = 0; i < 4; i++) {
        int idx = threadIdx.x + i*256;
        write_act(row, idx, (x[i] - mean) * rstd * g[idx] + be[idx]);
    }
}

__global__ __launch_bounds__(256) void add_ln_kernel(const float* __restrict__ g,
                                                     const float* __restrict__ be)
{
    const size_t base = (size_t)blockIdx.x * D_;
    float x[4]; float s = 0.f, ss = 0.f;
#pragma unroll
    for (int i = 0; i < 4; i++) {
        int idx = threadIdx.x + i*256;
        x[i] = g_h[base + idx] + g_ctx[base + idx];
        s += x[i]; ss += x[i]*x[i];
    }
    float mean, rstd;
    ln_stats(s, ss, mean, rstd);
#pragma unroll
    for (int i = 0; i < 4; i++) {
        int idx = threadIdx.x + i*256;
        write_act(blockIdx.x, idx, (x[i] - mean) * rstd * g[idx] + be[idx]);
    }
}

// ======================= driver =============================================
#define SMEM128 ((3*128*40 + 3*128*40)*2)   // 61440
#define SMEM64  ((3*128*40 + 3*64*40)*2)    // 46080

template<int BN, class Epi>
static void set_smem(int bytes) {
    cudaFuncSetAttribute(gemm_k<BN, Epi>,
                         cudaFuncAttributeMaxDynamicSharedMemorySize, bytes);
}

extern "C" void kernel_launch(void* const* d_in, const int* in_sizes, int n_in,
                              void* d_out, int out_size)
{
    (void)in_sizes; (void)n_in; (void)out_size;
    const int*   ids  = (const int*)  d_in[0];
    const float* mask = (const float*)d_in[1];
    const float* tok  = (const float*)d_in[2];
    const float* pos  = (const float*)d_in[3];
    const float* ln0g = (const float*)d_in[4];
    const float* ln0b = (const float*)d_in[5];
    const float* Wq   = (const float*)d_in[6];
    const float* bq   = (const float*)d_in[7];
    const float* Wk   = (const float*)d_in[8];
    const float* bk   = (const float*)d_in[9];
    const float* Wv   = (const float*)d_in[10];
    const float* bv   = (const float*)d_in[11];
    const float* ln1g = (const float*)d_in[12];
    const float* ln1b = (const float*)d_in[13];
    const float* W1   = (const float*)d_in[14];
    const float* b1   = (const float*)d_in[15];
    const float* W2   = (const float*)d_in[16];
    const float* b2   = (const float*)d_in[17];
    const float* ln2g = (const float*)d_in[18];
    const float* ln2b = (const float*)d_in[19];
    const float* Wlm  = (const float*)d_in[20];

    set_smem<128, EpiQs>(SMEM128);
    set_smem<128, EpiKs>(SMEM128);
    set_smem<128, EpiF32>(SMEM128);
    set_smem<128, EpiGelu>(SMEM128);
    set_smem<128, EpiScore>(SMEM128);
    set_smem<64,  EpiCtx>(SMEM64);

    bf16 *wq, *wk, *wv, *w1, *w2, *wlm, *aa, *qa, *ka, *va, *ffa, *pa;
    float *vbuf, *ctxp;
    cudaGetSymbolAddress((void**)&wq,  g_wq);
    cudaGetSymbolAddress((void**)&wk,  g_wk);
    cudaGetSymbolAddress((void**)&wv,  g_wv);
    cudaGetSymbolAddress((void**)&w1,  g_w1);
    cudaGetSymbolAddress((void**)&w2,  g_w2);
    cudaGetSymbolAddress((void**)&wlm, g_wlm);
    cudaGetSymbolAddress((void**)&aa,  g_aa);
    cudaGetSymbolAddress((void**)&qa,  g_qa);
    cudaGetSymbolAddress((void**)&ka,  g_ka);
    cudaGetSymbolAddress((void**)&va,  g_va);
    cudaGetSymbolAddress((void**)&ffa, g_ffa);
    cudaGetSymbolAddress((void**)&pa,  g_pa);
    cudaGetSymbolAddress((void**)&vbuf, g_v);
    cudaGetSymbolAddress((void**)&ctxp, g_ctx);

    // weight conversion: transpose + hi/lo split into augmented-K layout
    wsplit_kernel<<<dim3(D_/32,  D_/32,  L_), 256>>>(Wq,  wq,  D_,  D_);
    wsplit_kernel<<<dim3(D_/32,  D_/32,  L_), 256>>>(Wk,  wk,  D_,  D_);
    wsplit_kernel<<<dim3(D_/32,  D_/32,  L_), 256>>>(Wv,  wv,  D_,  D_);
    wsplit_kernel<<<dim3(FF_/32, D_/32,  L_), 256>>>(W1,  w1,  D_,  FF_);
    wsplit_kernel<<<dim3(D_/32,  FF_/32, L_), 256>>>(W2,  w2,  FF_, D_);
    wsplit_kernel<<<dim3(V_/32,  D_/32,  1 ), 256>>>(Wlm, wlm, D_,  V_);

    embed_ln_kernel<<<ROWS_, 256>>>(ids, tok, pos, ln0g, ln0b);

    const size_t WDD = (size_t)D_*KA_D;      // per-layer aug Wq/Wk/Wv
    const size_t W1S = (size_t)FF_*KA_D;
    const size_t W2S = (size_t)D_*KA_FF;

    for (int l = 0; l < L_; l++) {
        gemm_k<128, EpiQs><<<dim3(D_/128, ROWS_/128, 1), 256, SMEM128>>>(
            aa, wq + l*WDD, KA_D, 0, 0, EpiQs{bq + (size_t)l*D_});
        gemm_k<128, EpiKs><<<dim3(D_/128, ROWS_/128, 1), 256, SMEM128>>>(
            aa, wk + l*WDD, KA_D, 0, 0, EpiKs{bk + (size_t)l*D_});
        gemm_k<128, EpiF32><<<dim3(D_/128, ROWS_/128, 1), 256, SMEM128>>>(
            aa, wv + l*WDD, KA_D, 0, 0, EpiF32{vbuf, bv + (size_t)l*D_, D_});

        vtrans_kernel<<<dim3(S_/32, DH_/32, B_*H_), 256>>>();

        gemm_k<128, EpiScore><<<dim3(S_/128, S_/128, B_*H_), 256, SMEM128>>>(
            qa, ka, KA_DH, (size_t)S_*KA_DH, (size_t)S_*KA_DH, EpiScore{mask});
        softmax_split_kernel<<<B_*H_*S_, 256>>>();
        gemm_k<64, EpiCtx><<<dim3(1, S_/128, B_*H_), 256, SMEM64>>>(
            pa, va, KA_D, (size_t)S_*KA_D, (size_t)DH_*KA_D, EpiCtx{});

        add_ln_kernel<<<ROWS_, 256>>>(ln1g + (size_t)l*D_, ln1b + (size_t)l*D_);

        gemm_k<128, EpiGelu><<<dim3(FF_/128, ROWS_/128, 1), 256, SMEM128>>>(
            aa, w1 + l*W1S, KA_D, 0, 0, EpiGelu{b1 + (size_t)l*FF_});
        gemm_k<128, EpiF32><<<dim3(D_/128, ROWS_/128, 1), 256, SMEM128>>>(
            ffa, w2 + l*W2S, KA_FF, 0, 0, EpiF32{ctxp, b2 + (size_t)l*D_, D_});

        add_ln_kernel<<<ROWS_, 256>>>(ln2g + (size_t)l*D_, ln2b + (size_t)l*D_);
    }

    gemm_k<128, EpiF32><<<dim3(V_/128, ROWS_/128, 1), 256, SMEM128>>>(
        aa, wlm, KA_D, 0, 0, EpiF32{(float*)d_out, nullptr, V_});
}

// round 10
// speedup vs baseline: 2.0488x; 1.2642x over previous
#include <cuda_runtime.h>
#include <cuda_bf16.h>
#include <math.h>
#include <stdint.h>

typedef __nv_bfloat16 bf16;

#define D_  1024
#define S_  1024
#define B_  2
#define H_  16
#define DH_ 64
#define FF_ 4096
#define V_  32000
#define L_  12
#define ROWS_ (B_*S_)   // 2048
#define KA_D  3072      // 3*D
#define KA_FF 12288     // 3*FF
#define KA_DH 192       // 3*DH

// ======================= scratch (device globals) ===========================
__device__ __align__(256) float g_h  [ROWS_*D_];
__device__ __align__(256) float g_ctx[ROWS_*D_];
__device__ __align__(256) float g_sc [(size_t)B_*H_*S_*S_];

__device__ __align__(256) bf16 g_aa [(size_t)ROWS_*KA_D];            // A-layout acts
__device__ __align__(256) bf16 g_qa [(size_t)B_*H_*S_*KA_DH];        // Q aug per head
__device__ __align__(256) bf16 g_ka [(size_t)B_*H_*S_*KA_DH];        // K aug per head
__device__ __align__(256) bf16 g_va [(size_t)B_*H_*DH_*KA_D];        // V^T aug
__device__ __align__(256) bf16 g_ffa[(size_t)ROWS_*KA_FF];           // gelu out aug
__device__ __align__(256) bf16 g_pa [(size_t)B_*H_*S_*KA_D];         // probs aug

__device__ __align__(256) bf16 g_wq [(size_t)L_*D_*KA_D];
__device__ __align__(256) bf16 g_wk [(size_t)L_*D_*KA_D];
__device__ __align__(256) bf16 g_wv [(size_t)L_*D_*KA_D];
__device__ __align__(256) bf16 g_w1 [(size_t)L_*FF_*KA_D];
__device__ __align__(256) bf16 g_w2 [(size_t)L_*D_*KA_FF];
__device__ __align__(256) bf16 g_wlm[(size_t)V_*KA_D];

// ======================= helpers ============================================
__device__ __forceinline__ uint32_t smem_to_u32(const void* p) {
    uint32_t a;
    asm("{ .reg .u64 t; cvta.to.shared.u64 t, %1; cvt.u32.u64 %0, t; }"
        : "=r"(a) : "l"(p));
    return a;
}
__device__ __forceinline__ void cp16(bf16* s, const bf16* g) {
    uint32_t sa = smem_to_u32(s);
    asm volatile("cp.async.cg.shared.global [%0], [%1], 16;" :: "r"(sa), "l"(g));
}
#define CP_COMMIT() asm volatile("cp.async.commit_group;" ::: "memory")

#define LDSM4(R0,R1,R2,R3,ADDR) \
    asm volatile("ldmatrix.sync.aligned.m8n8.x4.shared.b16 {%0,%1,%2,%3}, [%4];" \
        : "=r"(R0), "=r"(R1), "=r"(R2), "=r"(R3) : "r"(ADDR))

#define MMA16816(C0,C1,C2,C3,A0,A1,A2,A3,B0,B1) \
    asm volatile("mma.sync.aligned.m16n8k16.row.col.f32.bf16.bf16.f32 " \
        "{%0,%1,%2,%3}, {%4,%5,%6,%7}, {%8,%9}, {%0,%1,%2,%3};" \
        : "+f"(C0), "+f"(C1), "+f"(C2), "+f"(C3) \
        : "r"(A0), "r"(A1), "r"(A2), "r"(A3), "r"(B0), "r"(B1))

__device__ __forceinline__ void split2(float v, bf16& h, bf16& l) {
    h = __float2bfloat16(v);
    l = __float2bfloat16(v - __bfloat162float(h));
}

// ======================= epilogue functors ==================================
struct EpiF32 {      // fp32 out (+opt bias)
    float* C; const float* bias; int ldc;
    __device__ void operator()(int z, int r, int c, float v) const {
        if (bias) v += bias[c];
        C[(size_t)r*ldc + c] = v;
    }
};
struct EpiQKV {      // z=0: Q split, z=1: K split, z=2: V transpose-split
    const float *bq, *bk, *bv;
    __device__ void operator()(int z, int r, int c, float v) const {
        int hh = c >> 6, d = c & 63;
        int b = r >> 10, s = r & 1023;
        if (z == 0) {
            v += bq[c];
            size_t base = ((size_t)((b << 4) + hh) * S_ + s) * KA_DH + d;
            bf16 h, l; split2(v, h, l);
            g_qa[base] = h; g_qa[base + 64] = l; g_qa[base + 128] = h;
        } else if (z == 1) {
            v += bk[c];
            size_t base = ((size_t)((b << 4) + hh) * S_ + s) * KA_DH + d;
            bf16 h, l; split2(v, h, l);
            g_ka[base] = h; g_ka[base + 64] = h; g_ka[base + 128] = l;
        } else {
            v += bv[c];
            size_t o = ((size_t)((b << 4) + hh) * DH_ + d) * KA_D + s;
            bf16 h, l; split2(v, h, l);
            g_va[o] = h; g_va[o + S_] = h; g_va[o + 2*S_] = l;
        }
    }
};
struct EpiGelu {     // FF1: bias + gelu + split -> g_ffa (h,l,h)
    const float* bias;
    __device__ void operator()(int z, int r, int c, float v) const {
        v += bias[c];
        v = v * 0.5f * (1.0f + erff(v * 0.70710678118654752f));
        bf16 h, l; split2(v, h, l);
        size_t base = (size_t)r * KA_FF + c;
        g_ffa[base] = h; g_ffa[base + FF_] = l; g_ffa[base + 2*FF_] = h;
    }
};
struct EpiScore {    // scores: scale + mask bias -> g_sc fp32
    const float* mask;
    __device__ void operator()(int z, int r, int c, float v) const {
        int b = z >> 4;
        g_sc[(size_t)z*S_*S_ + (size_t)r*S_ + c] =
            v * 0.125f + (1.0f - mask[b*S_ + c]) * -10000.0f;
    }
};
struct EpiCtx {      // ctx: fp32 -> g_ctx at head cols
    __device__ void operator()(int z, int r, int c, float v) const {
        int b = z >> 4, hh = z & 15;
        g_ctx[((size_t)(b * S_) + r) * D_ + hh*64 + c] = v;
    }
};

// ======================= pipelined mma.sync GEMM core =======================
// 128-thread CTA, 4 warps in 2x2, warp tile 64 x BN/2, BK=32, 4 stages.
template<int BN>
__device__ __forceinline__ void load_stage(const bf16* Ap, const bf16* Bp,
                                           bf16* As, bf16* Bs,
                                           int st, int k0, int K, int tid)
{
    constexpr int LDS = 40, ASZ = 128*LDS, BSZ = BN*LDS;
#pragma unroll
    for (int i = 0; i < 4; i++) {
        int ch = tid + i*128;
        int row = ch >> 2, c = ch & 3;
        cp16(As + st*ASZ + row*LDS + c*8, Ap + (size_t)row*K + k0 + c*8);
    }
#pragma unroll
    for (int i = 0; i < BN/32; i++) {
        int ch = tid + i*128;
        int row = ch >> 2, c = ch & 3;
        cp16(Bs + st*BSZ + row*LDS + c*8, Bp + (size_t)row*K + k0 + c*8);
    }
    CP_COMMIT();
}

template<int BN, class Epi>
__device__ __forceinline__ void gemm_core(const bf16* __restrict__ Ap,
                                          const bf16* __restrict__ Bp,
                                          int K, int z, int by, int bx,
                                          const Epi& epi)
{
    constexpr int NT  = BN / 16;       // n8-tiles per warp (warp tile 64 x BN/2)
    constexpr int LDS = 40;
    constexpr int ASZ = 128*LDS, BSZ = BN*LDS;
    constexpr int NSTG = 4;
    extern __shared__ bf16 sm[];
    bf16* As = sm;
    bf16* Bs = sm + NSTG*ASZ;

    const int tid = threadIdx.x, lane = tid & 31, wid = tid >> 5;
    const int wr = wid >> 1, wc = wid & 1;

    float acc[4][NT][4];
#pragma unroll
    for (int i = 0; i < 4; i++)
#pragma unroll
        for (int j = 0; j < NT; j++)
#pragma unroll
            for (int k = 0; k < 4; k++) acc[i][j][k] = 0.f;

    const uint32_t smBase = smem_to_u32(sm);
    const uint32_t aOff = (((lane & 15)*LDS) + ((lane >> 4) & 1)*8) * 2;
    const uint32_t bOff = ((((lane & 7) + ((lane >> 4) << 3))*LDS) + ((lane >> 3) & 1)*8) * 2;

    const int NK = K >> 5;
    load_stage<BN>(Ap, Bp, As, Bs, 0, 0,  K, tid);
    load_stage<BN>(Ap, Bp, As, Bs, 1, 32, K, tid);
    load_stage<BN>(Ap, Bp, As, Bs, 2, 64, K, tid);

    for (int it = 0; it < NK; it++) {
        const int rem = NK - 1 - it;
        if (rem >= 2)      asm volatile("cp.async.wait_group 2;" ::: "memory");
        else if (rem == 1) asm volatile("cp.async.wait_group 1;" ::: "memory");
        else               asm volatile("cp.async.wait_group 0;" ::: "memory");
        __syncthreads();
        const int nx = it + 3;
        if (nx < NK) load_stage<BN>(Ap, Bp, As, Bs, nx & 3, nx << 5, K, tid);

        const int st = it & 3;
        const uint32_t aS = smBase + (uint32_t)(st*ASZ + wr*64*LDS)*2 + aOff;
        const uint32_t bS = smBase + (uint32_t)(NSTG*ASZ + st*BSZ + wc*(BN/2)*LDS)*2 + bOff;
#pragma unroll
        for (int kk = 0; kk < 2; kk++) {
            uint32_t af[4][4];
#pragma unroll
            for (int mt = 0; mt < 4; mt++)
                LDSM4(af[mt][0], af[mt][1], af[mt][2], af[mt][3],
                      aS + (uint32_t)(mt*16*LDS + kk*16)*2);
            uint32_t bfr[NT][2];
#pragma unroll
            for (int np = 0; np < NT/2; np++) {
                uint32_t r0, r1, r2, r3;
                LDSM4(r0, r1, r2, r3, bS + (uint32_t)(np*16*LDS + kk*16)*2);
                bfr[2*np][0] = r0; bfr[2*np][1] = r1;
                bfr[2*np+1][0] = r2; bfr[2*np+1][1] = r3;
            }
#pragma unroll
            for (int mt = 0; mt < 4; mt++)
#pragma unroll
                for (int nt = 0; nt < NT; nt++)
                    MMA16816(acc[mt][nt][0], acc[mt][nt][1], acc[mt][nt][2], acc[mt][nt][3],
                             af[mt][0], af[mt][1], af[mt][2], af[mt][3],
                             bfr[nt][0], bfr[nt][1]);
        }
    }

    const int lr = lane >> 2, lc = (lane & 3) << 1;
#pragma unroll
    for (int mt = 0; mt < 4; mt++)
#pragma unroll
        for (int nt = 0; nt < NT; nt++) {
            int r0 = by*128 + wr*64 + mt*16 + lr;
            int c0 = bx*BN + wc*(BN/2) + nt*8 + lc;
            epi(z, r0,     c0,     acc[mt][nt][0]);
            epi(z, r0,     c0 + 1, acc[mt][nt][1]);
            epi(z, r0 + 8, c0,     acc[mt][nt][2]);
            epi(z, r0 + 8, c0 + 1, acc[mt][nt][3]);
        }
}

template<int BN, class Epi>
__global__ __launch_bounds__(128, 2)
void gemm_k(const bf16* __restrict__ A, const bf16* __restrict__ B, int K,
            size_t sA, size_t sB, Epi epi)
{
    const int z = blockIdx.z;
    const bf16* Ap = A + (size_t)z*sA + (size_t)blockIdx.y * 128 * K;
    const bf16* Bp = B + (size_t)z*sB + (size_t)blockIdx.x * BN  * K;
    gemm_core<BN, Epi>(Ap, Bp, K, z, blockIdx.y, blockIdx.x, epi);
}

__global__ __launch_bounds__(128, 2)
void qkv_k(const bf16* __restrict__ A,
           const bf16* __restrict__ Wq, const bf16* __restrict__ Wk,
           const bf16* __restrict__ Wv, EpiQKV epi)
{
    const int z = blockIdx.z;
    const bf16* W = (z == 0) ? Wq : (z == 1) ? Wk : Wv;
    const bf16* Ap = A + (size_t)blockIdx.y * 128 * KA_D;
    const bf16* Bp = W + (size_t)blockIdx.x * 128 * KA_D;
    gemm_core<128, EpiQKV>(Ap, Bp, KA_D, z, blockIdx.y, blockIdx.x, epi);
}

// ======================= weight transpose+split (B-layout) ==================
// W[K,N] fp32 -> out[N, 3K] bf16: [Wh | Wh | Wl]
__global__ __launch_bounds__(256) void wsplit_kernel(const float* __restrict__ W,
        bf16* __restrict__ out, int K, int N)
{
    __shared__ float t[32][33];
    const size_t mat  = (size_t)blockIdx.z * K * N;
    const size_t mato = (size_t)blockIdx.z * K * N * 3;
    const int n0 = blockIdx.x*32, k0 = blockIdx.y*32;
    const int tx = threadIdx.x & 31, ty = threadIdx.x >> 5;
#pragma unroll
    for (int i = 0; i < 4; i++) {
        int k = k0 + ty*4 + i;
        t[ty*4+i][tx] = W[mat + (size_t)k*N + n0 + tx];
    }
    __syncthreads();
#pragma unroll
    for (int i = 0; i < 4; i++) {
        int n = n0 + ty*4 + i;
        float v = t[tx][ty*4+i];
        bf16 h, l; split2(v, h, l);
        size_t o = mato + (size_t)n*3*K + k0 + tx;
        out[o] = h; out[o + K] = h; out[o + 2*K] = l;
    }
}

// ======================= softmax (fp32 in -> aug bf16 out) ==================
__global__ __launch_bounds__(256) void softmax_split_kernel()
{
    const size_t base = (size_t)blockIdx.x * S_;
    const int tid = threadIdx.x;
    float x[4];
    float mx = -1e30f;
#pragma unroll
    for (int i = 0; i < 4; i++) {
        x[i] = g_sc[base + tid + i*256];
        mx = fmaxf(mx, x[i]);
    }
#pragma unroll
    for (int off = 16; off; off >>= 1)
        mx = fmaxf(mx, __shfl_xor_sync(0xffffffffu, mx, off));
    __shared__ float red[8];
    if ((tid & 31) == 0) red[tid >> 5] = mx;
    __syncthreads();
    if (tid == 0) {
        float v = red[0];
#pragma unroll
        for (int i = 1; i < 8; i++) v = fmaxf(v, red[i]);
        red[0] = v;
    }
    __syncthreads();
    mx = red[0];
    __syncthreads();
    float sum = 0.f;
#pragma unroll
    for (int i = 0; i < 4; i++) { x[i] = expf(x[i] - mx); sum += x[i]; }
#pragma unroll
    for (int off = 16; off; off >>= 1)
        sum += __shfl_xor_sync(0xffffffffu, sum, off);
    if ((tid & 31) == 0) red[tid >> 5] = sum;
    __syncthreads();
    if (tid == 0) {
        float v = 0.f;
#pragma unroll
        for (int i = 0; i < 8; i++) v += red[i];
        red[0] = 1.0f / v;
    }
    __syncthreads();
    const float inv = red[0];
    const size_t ob = (size_t)blockIdx.x * KA_D;
#pragma unroll
    for (int i = 0; i < 4; i++) {
        int idx = tid + i*256;
        float p = x[i] * inv;
        bf16 h, l; split2(p, h, l);
        g_pa[ob + idx] = h; g_pa[ob + S_ + idx] = l; g_pa[ob + 2*S_ + idx] = h;
    }
}

// ======================= LayerNorm (fp32 h + aug split out) =================
__device__ __forceinline__ void ln_stats(float s, float ss, float& mean, float& rstd)
{
#pragma unroll
    for (int off = 16; off; off >>= 1) {
        s  += __shfl_xor_sync(0xffffffffu, s,  off);
        ss += __shfl_xor_sync(0xffffffffu, ss, off);
    }
    __shared__ float rs[8], rss[8];
    const int w = threadIdx.x >> 5;
    if ((threadIdx.x & 31) == 0) { rs[w] = s; rss[w] = ss; }
    __syncthreads();
    if (threadIdx.x == 0) {
        float a = 0.f, bb = 0.f;
#pragma unroll
        for (int i = 0; i < 8; i++) { a += rs[i]; bb += rss[i]; }
        float mu  = a * (1.0f / 1024.0f);
        float var = bb * (1.0f / 1024.0f) - mu * mu;
        rs[0]  = mu;
        rss[0] = rsqrtf(var + 1e-5f);
    }
    __syncthreads();
    mean = rs[0];
    rstd = rss[0];
}

__device__ __forceinline__ void write_act(size_t row, int idx, float y)
{
    g_h[row*D_ + idx] = y;
    bf16 h, l; split2(y, h, l);
    size_t b3 = row*KA_D + idx;
    g_aa[b3] = h; g_aa[b3 + D_] = l; g_aa[b3 + 2*D_] = h;
}

__global__ __launch_bounds__(256) void embed_ln_kernel(const int* __restrict__ ids,
                                                       const float* __restrict__ tok,
                                                       const float* __restrict__ pos,
                                                       const float* __restrict__ g,
                                                       const float* __restrict__ be)
{
    const int row  = blockIdx.x;
    const int spos = row & (S_ - 1);
    const size_t tbase = (size_t)ids[row] * D_;
    const size_t pbase = (size_t)spos * D_;
    float x[4]; float s = 0.f, ss = 0.f;
#pragma unroll
    for (int i = 0; i < 4; i++) {
        int idx = threadIdx.x + i*256;
        x[i] = tok[tbase + idx] + pos[pbase + idx];
        s += x[i]; ss += x[i]*x[i];
    }
    float mean, rstd;
    ln_stats(s, ss, mean, rstd);
#pragma unroll
    for (int i = 0; i < 4; i++) {
        int idx = threadIdx.x + i*256;
        write_act(row, idx, (x[i] - mean) * rstd * g[idx] + be[idx]);
    }
}

__global__ __launch_bounds__(256) void add_ln_kernel(const float* __restrict__ g,
                                                     const float* __restrict__ be)
{
    const size_t base = (size_t)blockIdx.x * D_;
    float x[4]; float s = 0.f, ss = 0.f;
#pragma unroll
    for (int i = 0; i < 4; i++) {
        int idx = threadIdx.x + i*256;
        x[i] = g_h[base + idx] + g_ctx[base + idx];
        s += x[i]; ss += x[i]*x[i];
    }
    float mean, rstd;
    ln_stats(s, ss, mean, rstd);
#pragma unroll
    for (int i = 0; i < 4; i++) {
        int idx = threadIdx.x + i*256;
        write_act(blockIdx.x, idx, (x[i] - mean) * rstd * g[idx] + be[idx]);
    }
}

// ======================= driver =============================================
#define SMEM128 (4*(128*40 + 128*40)*2)   // 81920
#define SMEM64  (4*(128*40 +  64*40)*2)   // 61440

extern "C" void kernel_launch(void* const* d_in, const int* in_sizes, int n_in,
                              void* d_out, int out_size)
{
    (void)in_sizes; (void)n_in; (void)out_size;
    const int*   ids  = (const int*)  d_in[0];
    const float* mask = (const float*)d_in[1];
    const float* tok  = (const float*)d_in[2];
    const float* pos  = (const float*)d_in[3];
    const float* ln0g = (const float*)d_in[4];
    const float* ln0b = (const float*)d_in[5];
    const float* Wq   = (const float*)d_in[6];
    const float* bq   = (const float*)d_in[7];
    const float* Wk   = (const float*)d_in[8];
    const float* bk   = (const float*)d_in[9];
    const float* Wv   = (const float*)d_in[10];
    const float* bv   = (const float*)d_in[11];
    const float* ln1g = (const float*)d_in[12];
    const float* ln1b = (const float*)d_in[13];
    const float* W1   = (const float*)d_in[14];
    const float* b1   = (const float*)d_in[15];
    const float* W2   = (const float*)d_in[16];
    const float* b2   = (const float*)d_in[17];
    const float* ln2g = (const float*)d_in[18];
    const float* ln2b = (const float*)d_in[19];
    const float* Wlm  = (const float*)d_in[20];

    cudaFuncSetAttribute(qkv_k, cudaFuncAttributeMaxDynamicSharedMemorySize, SMEM128);
    cudaFuncSetAttribute(gemm_k<128, EpiScore>, cudaFuncAttributeMaxDynamicSharedMemorySize, SMEM128);
    cudaFuncSetAttribute(gemm_k<128, EpiGelu>,  cudaFuncAttributeMaxDynamicSharedMemorySize, SMEM128);
    cudaFuncSetAttribute(gemm_k<128, EpiF32>,   cudaFuncAttributeMaxDynamicSharedMemorySize, SMEM128);
    cudaFuncSetAttribute(gemm_k<64,  EpiF32>,   cudaFuncAttributeMaxDynamicSharedMemorySize, SMEM64);
    cudaFuncSetAttribute(gemm_k<64,  EpiCtx>,   cudaFuncAttributeMaxDynamicSharedMemorySize, SMEM64);

    bf16 *wq, *wk, *wv, *w1, *w2, *wlm, *aa, *qa, *ka, *va, *ffa, *pa;
    float *ctxp;
    cudaGetSymbolAddress((void**)&wq,  g_wq);
    cudaGetSymbolAddress((void**)&wk,  g_wk);
    cudaGetSymbolAddress((void**)&wv,  g_wv);
    cudaGetSymbolAddress((void**)&w1,  g_w1);
    cudaGetSymbolAddress((void**)&w2,  g_w2);
    cudaGetSymbolAddress((void**)&wlm, g_wlm);
    cudaGetSymbolAddress((void**)&aa,  g_aa);
    cudaGetSymbolAddress((void**)&qa,  g_qa);
    cudaGetSymbolAddress((void**)&ka,  g_ka);
    cudaGetSymbolAddress((void**)&va,  g_va);
    cudaGetSymbolAddress((void**)&ffa, g_ffa);
    cudaGetSymbolAddress((void**)&pa,  g_pa);
    cudaGetSymbolAddress((void**)&ctxp, g_ctx);

    // weight conversion: transpose + hi/lo split into augmented-K layout
    wsplit_kernel<<<dim3(D_/32,  D_/32,  L_), 256>>>(Wq,  wq,  D_,  D_);
    wsplit_kernel<<<dim3(D_/32,  D_/32,  L_), 256>>>(Wk,  wk,  D_,  D_);
    wsplit_kernel<<<dim3(D_/32,  D_/32,  L_), 256>>>(Wv,  wv,  D_,  D_);
    wsplit_kernel<<<dim3(FF_/32, D_/32,  L_), 256>>>(W1,  w1,  D_,  FF_);
    wsplit_kernel<<<dim3(D_/32,  FF_/32, L_), 256>>>(W2,  w2,  FF_, D_);
    wsplit_kernel<<<dim3(V_/32,  D_/32,  1 ), 256>>>(Wlm, wlm, D_,  V_);

    embed_ln_kernel<<<ROWS_, 256>>>(ids, tok, pos, ln0g, ln0b);

    const size_t WDD = (size_t)D_*KA_D;
    const size_t W1S = (size_t)FF_*KA_D;
    const size_t W2S = (size_t)D_*KA_FF;

    for (int l = 0; l < L_; l++) {
        qkv_k<<<dim3(D_/128, ROWS_/128, 3), 128, SMEM128>>>(
            aa, wq + l*WDD, wk + l*WDD, wv + l*WDD,
            EpiQKV{bq + (size_t)l*D_, bk + (size_t)l*D_, bv + (size_t)l*D_});

        gemm_k<128, EpiScore><<<dim3(S_/128, S_/128, B_*H_), 128, SMEM128>>>(
            qa, ka, KA_DH, (size_t)S_*KA_DH, (size_t)S_*KA_DH, EpiScore{mask});
        softmax_split_kernel<<<B_*H_*S_, 256>>>();
        gemm_k<64, EpiCtx><<<dim3(1, S_/128, B_*H_), 128, SMEM64>>>(
            pa, va, KA_D, (size_t)S_*KA_D, (size_t)DH_*KA_D, EpiCtx{});

        add_ln_kernel<<<ROWS_, 256>>>(ln1g + (size_t)l*D_, ln1b + (size_t)l*D_);

        gemm_k<128, EpiGelu><<<dim3(FF_/128, ROWS_/128, 1), 128, SMEM128>>>(
            aa, w1 + l*W1S, KA_D, 0, 0, EpiGelu{b1 + (size_t)l*FF_});
        gemm_k<64, EpiF32><<<dim3(D_/64, ROWS_/128, 1), 128, SMEM64>>>(
            ffa, w2 + l*W2S, KA_FF, 0, 0, EpiF32{ctxp, b2 + (size_t)l*D_, D_});

        add_ln_kernel<<<ROWS_, 256>>>(ln2g + (size_t)l*D_, ln2b + (size_t)l*D_);
    }

    gemm_k<128, EpiF32><<<dim3(V_/128, ROWS_/128, 1), 128, SMEM128>>>(
        aa, wlm, KA_D, 0, 0, EpiF32{(float*)d_out, nullptr, V_});
}